// round 16
// baseline (speedup 1.0000x reference)
#include <cuda_runtime.h>
#include <cuda_fp16.h>
#include <cstdint>

#define DD    1024
#define TT    2048
#define BB    2
#define MTOT  4096
#define HH    16
#define DHD   64
#define RR    8
#define NQKV  3072

// ---- GEMM tiling: 128x128 CTA tile, 2 smem tiles/stage (A, B), 3 stages
#define TM 128
#define TN 128
#define KSTEP 32
#define NK (DD / KSTEP)              // 32
#define ROWB 80
#define TILE_BYTES (128 * ROWB)      // 10240
#define STAGE_BYTES (2 * TILE_BYTES) // 20480
#define NSTAGE 3
#define SMEM_TOTAL (NSTAGE * STAGE_BYTES) // 61440

// ---- flash tiling: 128-key stages, 3 stages; 4 warps x 32 q-rows
#define FROWB 144
#define KB    (128 * FROWB)          // 18432 bytes: K block of 128 rows
#define FSTAGE (2 * KB)              // 36864  (K128, V128)
#define FSMEM (3 * FSTAGE)           // 110592

// Q scale: 1/sqrt(64) * log2(e)  (softmax done in exp2 domain)
#define QSCALE (0.125f * 1.44269504088896f)

// ---- scratch ----
__device__ __half g_Xh [MTOT * DD];
__device__ __half g_Wh [NQKV * DD];
__device__ __half g_WOh[DD * DD];
__device__ __half g_Qh [MTOT * DD];
__device__ __half g_Kh [MTOT * DD];
__device__ __half g_Vh [MTOT * DD];
__device__ __half g_AOh[MTOT * DD];

// ---------------- PTX helpers ----------------
__device__ __forceinline__ uint32_t smem_u32(const void* p) {
    uint32_t a;
    asm("{ .reg .u64 t; cvta.to.shared.u64 t, %1; cvt.u32.u64 %0, t; }" : "=r"(a) : "l"(p));
    return a;
}
#define CP_ASYNC16(dst, src) \
    asm volatile("cp.async.cg.shared.global [%0], [%1], 16;" :: "r"(dst), "l"(src))
#define CP_COMMIT()   asm volatile("cp.async.commit_group;" ::: "memory")
#define CP_WAIT(n)    asm volatile("cp.async.wait_group %0;" :: "n"(n) : "memory")

__device__ __forceinline__ void ldsm4(uint32_t* r, uint32_t addr) {
    asm volatile("ldmatrix.sync.aligned.m8n8.x4.shared.b16 {%0,%1,%2,%3}, [%4];"
                 : "=r"(r[0]), "=r"(r[1]), "=r"(r[2]), "=r"(r[3]) : "r"(addr));
}
__device__ __forceinline__ void ldsm4t(uint32_t* r, uint32_t addr) {
    asm volatile("ldmatrix.sync.aligned.m8n8.x4.trans.shared.b16 {%0,%1,%2,%3}, [%4];"
                 : "=r"(r[0]), "=r"(r[1]), "=r"(r[2]), "=r"(r[3]) : "r"(addr));
}
__device__ __forceinline__ void mma16816(float* c, const uint32_t* a, const uint32_t* b) {
    asm volatile("mma.sync.aligned.m16n8k16.row.col.f32.f16.f16.f32 "
                 "{%0,%1,%2,%3}, {%4,%5,%6,%7}, {%8,%9}, {%0,%1,%2,%3};"
                 : "+f"(c[0]), "+f"(c[1]), "+f"(c[2]), "+f"(c[3])
                 : "r"(a[0]), "r"(a[1]), "r"(a[2]), "r"(a[3]), "r"(b[0]), "r"(b[1]));
}

// ---------------- single fused prep kernel ----------------
#define N_X  (MTOT * DD)
#define N_W  (NQKV * DD)
#define N_WO (DD * DD)
__global__ void prep_all(const float* __restrict__ x,
                         const float* __restrict__ wq, const float* __restrict__ qA,
                         const float* __restrict__ qB, const float* __restrict__ wk,
                         const float* __restrict__ wv, const float* __restrict__ vA,
                         const float* __restrict__ vB, const float* __restrict__ wo,
                         __half* __restrict__ Xh, __half* __restrict__ Wh,
                         __half* __restrict__ WOh) {
    int i = blockIdx.x * blockDim.x + threadIdx.x;
    if (i < N_X) {
        Xh[i] = __float2half_rn(x[i]);
        return;
    }
    i -= N_X;
    if (i < N_W) {
        int o = i / DD, c = i % DD;
        float v;
        if (o < 1024) {
            v = wq[o * DD + c];
#pragma unroll
            for (int r = 0; r < RR; r++) v += 2.0f * qB[o * RR + r] * qA[r * DD + c];
        } else if (o < 2048) {
            v = wk[(o - 1024) * DD + c];
        } else {
            int oo = o - 2048;
            v = wv[oo * DD + c];
#pragma unroll
            for (int r = 0; r < RR; r++) v += 2.0f * vB[oo * RR + r] * vA[r * DD + c];
        }
        Wh[i] = __float2half_rn(v);
        return;
    }
    i -= N_W;
    if (i < N_WO) WOh[i] = __float2half_rn(wo[i]);
}

// ---------------- single-term fp16 GEMM (fp32 accum): C = A @ B^T ----------------
__device__ __forceinline__ void load_stage(
    uint32_t stage_base, const __half* __restrict__ A, const __half* __restrict__ B,
    int m0, int n0, int kc, int tid)
{
#pragma unroll
    for (int t = 0; t < 2; t++) {
        const __half* base = (t == 0 ? A : B) + (size_t)(t == 0 ? m0 : n0) * DD + kc * KSTEP;
        uint32_t dst_tile = stage_base + t * TILE_BYTES;
#pragma unroll
        for (int i = 0; i < 2; i++) {
            int idx = tid + i * 256;
            int row = idx >> 2, c = idx & 3;
            CP_ASYNC16(dst_tile + row * ROWB + c * 16,
                       (const char*)(base + (size_t)row * DD) + c * 16);
        }
    }
}

// MODE 0: fp32 C.  MODE 1: fused QKV epilogue (per-head fp16, Q scaled into exp2 domain)
template<int MODE>
__global__ __launch_bounds__(256, 2) void gemm_ts(
    const __half* __restrict__ A, const __half* __restrict__ B,
    float* __restrict__ C, int Ntot,
    __half* __restrict__ Qh, __half* __restrict__ Kh, __half* __restrict__ Vh)
{
    extern __shared__ char smem[];
    uint32_t sb = smem_u32(smem);
    int tid = threadIdx.x;
    int wid = tid >> 5, lane = tid & 31;
    int wm = (wid & 3) * 32;
    int wn = (wid >> 2) * 64;
    int m0 = blockIdx.y * TM, n0 = blockIdx.x * TN;

    uint32_t aoff = (uint32_t)(wm + (lane & 15)) * ROWB + (lane >> 4) * 16;
    uint32_t boff = (uint32_t)(wn + (lane & 7) + ((lane >> 4) << 3)) * ROWB
                  + ((lane >> 3) & 1) * 16;

    float acc[2][8][4];
#pragma unroll
    for (int i = 0; i < 2; i++)
#pragma unroll
        for (int j = 0; j < 8; j++)
#pragma unroll
            for (int k = 0; k < 4; k++) acc[i][j][k] = 0.0f;

    load_stage(sb, A, B, m0, n0, 0, tid);
    CP_COMMIT();
    load_stage(sb + STAGE_BYTES, A, B, m0, n0, 1, tid);
    CP_COMMIT();

    int sidx = 0;
    for (int c = 0; c < NK; c++) {
        uint32_t st = sb + sidx * STAGE_BYTES;
        if (c + 1 < NK) { CP_WAIT(1); } else { CP_WAIT(0); }
        __syncthreads();
        if (c + 2 < NK) {
            int s2 = sidx + 2; if (s2 >= NSTAGE) s2 -= NSTAGE;
            load_stage(sb + s2 * STAGE_BYTES, A, B, m0, n0, c + 2, tid);
            CP_COMMIT();
        }

        uint32_t baseA = st + aoff;
        uint32_t baseB = st + TILE_BYTES + boff;

#pragma unroll
        for (int kk = 0; kk < 2; kk++) {
            uint32_t koff = kk * 32;
            uint32_t a[2][4], b[4][4];
#pragma unroll
            for (int mt = 0; mt < 2; mt++)
                ldsm4(a[mt], baseA + mt * 16 * ROWB + koff);
#pragma unroll
            for (int np = 0; np < 4; np++)
                ldsm4(b[np], baseB + np * 16 * ROWB + koff);
#pragma unroll
            for (int mt = 0; mt < 2; mt++)
#pragma unroll
                for (int np = 0; np < 4; np++) {
                    mma16816(acc[mt][np*2],   a[mt], &b[np][0]);
                    mma16816(acc[mt][np*2+1], a[mt], &b[np][2]);
                }
        }
        if (++sidx >= NSTAGE) sidx -= NSTAGE;
    }

    if (MODE == 0) {
        int rbase = m0 + wm + (lane >> 2);
        int cbase = n0 + wn + 2 * (lane & 3);
#pragma unroll
        for (int mt = 0; mt < 2; mt++)
#pragma unroll
            for (int nt = 0; nt < 8; nt++) {
                float* p0 = C + (size_t)(rbase + mt * 16) * Ntot + cbase + nt * 8;
                float* p1 = C + (size_t)(rbase + mt * 16 + 8) * Ntot + cbase + nt * 8;
                *(float2*)p0 = make_float2(acc[mt][nt][0], acc[mt][nt][1]);
                *(float2*)p1 = make_float2(acc[mt][nt][2], acc[mt][nt][3]);
            }
    } else {
        int colbase = n0 + wn;
        int sector = colbase >> 10;
        int h = (colbase & 1023) >> 6;
        int d0 = 2 * (lane & 3);
        float scale = (sector == 0) ? QSCALE : 1.0f;
        __half* D = (sector == 0) ? Qh : (sector == 1) ? Kh : Vh;
#pragma unroll
        for (int mt = 0; mt < 2; mt++) {
            int mrow0 = m0 + wm + (lane >> 2) + mt * 16;
            int mrow1 = mrow0 + 8;
            size_t base0 = ((size_t)((mrow0 >> 11) * HH + h) * TT + (mrow0 & 2047)) * DHD + d0;
            size_t base1 = ((size_t)((mrow1 >> 11) * HH + h) * TT + (mrow1 & 2047)) * DHD + d0;
#pragma unroll
            for (int nt = 0; nt < 8; nt++) {
                *(__half2*)(D + base0 + nt * 8) =
                    __floats2half2_rn(acc[mt][nt][0] * scale, acc[mt][nt][1] * scale);
                *(__half2*)(D + base1 + nt * 8) =
                    __floats2half2_rn(acc[mt][nt][2] * scale, acc[mt][nt][3] * scale);
            }
        }
    }
}

// ---------------- flash attention: 4 warps x 32 q-rows, 128-key stages ----------------
// K/V fragments reused across the warp's two m16 row-groups (halved smem traffic);
// softmax exp2 in fp16x2 (one MUFU op per 2 elements) — MUFU no longer co-dominant.
__device__ __forceinline__ void flash_load_kv128(
    uint32_t st, const __half* __restrict__ Kh, const __half* __restrict__ Vh,
    int bh, int k0, int tid)
{
#pragma unroll
    for (int i = 0; i < 8; i++) {
        int idx = tid + i * 128;            // 0..1023
        int row = idx >> 3, c = idx & 7;    // 128 rows x 8 x 16B
        size_t krow = ((size_t)bh * TT + k0 + row) * DHD;
        CP_ASYNC16(st + row * FROWB + c * 16,      (const char*)(Kh + krow) + c * 16);
        CP_ASYNC16(st + KB + row * FROWB + c * 16, (const char*)(Vh + krow) + c * 16);
    }
}

__global__ __launch_bounds__(128, 2) void flash_mma(
    const __half* __restrict__ Qh, const __half* __restrict__ Kh,
    const __half* __restrict__ Vh, __half* __restrict__ AOh)
{
    extern __shared__ char smem[];
    uint32_t sb = smem_u32(smem);
    int tid = threadIdx.x, wid = tid >> 5, lane = tid & 31;
    int qblk = (TT / 128 - 1) - blockIdx.x;   // longest blocks first
    int bh = blockIdx.y;
    int q0 = qblk * 128;
    int wm = wid * 32;                        // warp owns 32 q-rows
    int nit = qblk + 1;                       // 128-key iterations
    int wrow_max = q0 + wm + 31;

    // ---- Q into smem (stage0 area), consume to regs
#pragma unroll
    for (int i = 0; i < 8; i++) {
        int idx = tid + i * 128;
        int row = idx >> 3, c = idx & 7;
        size_t qrow = ((size_t)bh * TT + q0 + row) * DHD;
        CP_ASYNC16(sb + row * FROWB + c * 16, (const char*)(Qh + qrow) + c * 16);
    }
    CP_COMMIT(); CP_WAIT(0);
    __syncthreads();
    uint32_t qf[2][4][4];
#pragma unroll
    for (int mt = 0; mt < 2; mt++) {
        uint32_t qaddr = sb + (uint32_t)(wm + mt * 16 + (lane & 15)) * FROWB + (lane >> 4) * 16;
#pragma unroll
        for (int s = 0; s < 4; s++)
            ldsm4(qf[mt][s], qaddr + s * 32);
    }
    __syncthreads();

    float o[2][8][4];
#pragma unroll
    for (int mt = 0; mt < 2; mt++)
#pragma unroll
        for (int j = 0; j < 8; j++)
#pragma unroll
            for (int k = 0; k < 4; k++) o[mt][j][k] = 0.0f;
    float lrow[2][2] = {{0.f, 0.f}, {0.f, 0.f}};

    flash_load_kv128(sb, Kh, Vh, bh, 0, tid);
    CP_COMMIT();
    if (nit > 1) {
        flash_load_kv128(sb + FSTAGE, Kh, Vh, bh, 128, tid);
        CP_COMMIT();
    }

    uint32_t bpat = (uint32_t)((lane & 7) + ((lane >> 4) << 3)) * FROWB + ((lane >> 3) & 1) * 16;
    uint32_t vpat = (uint32_t)(lane & 15) * FROWB + ((lane >> 4) << 4);

    int sidx = 0;
    for (int it = 0; it < nit; it++) {
        uint32_t st = sb + sidx * FSTAGE;
        if (it + 1 < nit) { CP_WAIT(1); } else { CP_WAIT(0); }
        __syncthreads();
        if (it + 2 < nit) {
            int s2 = sidx + 2; if (s2 >= 3) s2 -= 3;
            flash_load_kv128(sb + s2 * FSTAGE, Kh, Vh, bh, (it + 2) * 128, tid);
            CP_COMMIT();
        }

#pragma unroll
        for (int sub = 0; sub < 2; sub++) {
            int kb = it * 128 + sub * 64;
            if (kb > wrow_max) break;       // per-warp causal skip

            uint32_t subK = st + (uint32_t)(sub * 64) * FROWB;
            uint32_t subV = st + KB + (uint32_t)(sub * 64) * FROWB;

            // ---- S = Q K^T for both m16 row-groups (K frags reused)
            float s[2][8][4];
#pragma unroll
            for (int mt = 0; mt < 2; mt++)
#pragma unroll
                for (int j = 0; j < 8; j++)
#pragma unroll
                    for (int k = 0; k < 4; k++) s[mt][j][k] = 0.0f;
            uint32_t baseK = subK + bpat;
#pragma unroll
            for (int ks = 0; ks < 4; ks++) {
                uint32_t koff = ks * 32;
                uint32_t kbf[4][4];
#pragma unroll
                for (int np = 0; np < 4; np++)
                    ldsm4(kbf[np], baseK + np * 16 * FROWB + koff);
#pragma unroll
                for (int mt = 0; mt < 2; mt++)
#pragma unroll
                    for (int np = 0; np < 4; np++) {
                        mma16816(s[mt][np*2],   qf[mt][ks], &kbf[np][0]);
                        mma16816(s[mt][np*2+1], qf[mt][ks], &kbf[np][2]);
                    }
            }

            // ---- mask + static fp16x2 exp2 softmax + pack, per row-group
            uint32_t ph[2][8][2];
#pragma unroll
            for (int mt = 0; mt < 2; mt++) {
                int row0 = q0 + wm + mt * 16 + (lane >> 2);
                if (kb + 63 > row0) {
#pragma unroll
                    for (int j = 0; j < 8; j++) {
                        int colb = kb + j * 8 + 2 * (lane & 3);
                        if (colb     > row0)     s[mt][j][0] = -1e30f;
                        if (colb + 1 > row0)     s[mt][j][1] = -1e30f;
                        if (colb     > row0 + 8) s[mt][j][2] = -1e30f;
                        if (colb + 1 > row0 + 8) s[mt][j][3] = -1e30f;
                    }
                }
                __half2 la = __floats2half2_rn(0.f, 0.f);
                __half2 lb = __floats2half2_rn(0.f, 0.f);
#pragma unroll
                for (int j = 0; j < 8; j++) {
                    __half2 h0 = h2exp2(__floats2half2_rn(s[mt][j][0], s[mt][j][1]));
                    __half2 h1 = h2exp2(__floats2half2_rn(s[mt][j][2], s[mt][j][3]));
                    ph[mt][j][0] = *(uint32_t*)&h0; ph[mt][j][1] = *(uint32_t*)&h1;
                    la = __hadd2(la, h0);
                    lb = __hadd2(lb, h1);
                }
                float2 fa = __half22float2(la);
                float2 fb = __half22float2(lb);
                lrow[mt][0] += fa.x + fa.y;
                lrow[mt][1] += fb.x + fb.y;
            }

            // ---- O += P V for both row-groups (V frags reused)
            uint32_t baseV = subV + vpat;
#pragma unroll
            for (int ks = 0; ks < 4; ks++) {
                uint32_t roff = ks * 16 * FROWB;
                uint32_t vb[4][4];
#pragma unroll
                for (int np = 0; np < 4; np++)
                    ldsm4t(vb[np], baseV + roff + np * 32);
#pragma unroll
                for (int mt = 0; mt < 2; mt++) {
                    uint32_t ath[4] = { ph[mt][2*ks][0], ph[mt][2*ks][1],
                                        ph[mt][2*ks+1][0], ph[mt][2*ks+1][1] };
#pragma unroll
                    for (int np = 0; np < 4; np++) {
                        mma16816(o[mt][np*2],   ath, &vb[np][0]);
                        mma16816(o[mt][np*2+1], ath, &vb[np][2]);
                    }
                }
            }
        }
        if (++sidx >= 3) sidx -= 3;
    }

    // ---- deferred row-sum reduction (once)
#pragma unroll
    for (int mt = 0; mt < 2; mt++)
#pragma unroll
        for (int g = 0; g < 2; g++) {
            lrow[mt][g] += __shfl_xor_sync(0xffffffff, lrow[mt][g], 1);
            lrow[mt][g] += __shfl_xor_sync(0xffffffff, lrow[mt][g], 2);
        }

    // ---- epilogue: normalize, fp16 AO
    int b = bh >> 4, h = bh & 15;
#pragma unroll
    for (int mt = 0; mt < 2; mt++) {
        float inv0 = 1.0f / lrow[mt][0], inv1 = 1.0f / lrow[mt][1];
        int r0 = q0 + wm + mt * 16 + (lane >> 2);
        size_t base0 = (size_t)(b * TT + r0) * DD + h * DHD + 2 * (lane & 3);
        size_t base1 = base0 + (size_t)8 * DD;
#pragma unroll
        for (int j = 0; j < 8; j++) {
            *(__half2*)(AOh + base0 + j * 8) =
                __floats2half2_rn(o[mt][j][0] * inv0, o[mt][j][1] * inv0);
            *(__half2*)(AOh + base1 + j * 8) =
                __floats2half2_rn(o[mt][j][2] * inv1, o[mt][j][3] * inv1);
        }
    }
}

// ---------------- launch ----------------
extern "C" void kernel_launch(void* const* d_in, const int* in_sizes, int n_in,
                              void* d_out, int out_size) {
    const float* x    = (const float*)d_in[0];
    const float* wq_w = (const float*)d_in[2];
    const float* wq_A = (const float*)d_in[3];
    const float* wq_B = (const float*)d_in[4];
    const float* wk_w = (const float*)d_in[5];
    const float* wv_w = (const float*)d_in[6];
    const float* wv_A = (const float*)d_in[7];
    const float* wv_B = (const float*)d_in[8];
    const float* wo_w = (const float*)d_in[9];
    float* out = (float*)d_out;

    static bool attr_set = false;
    if (!attr_set) {
        cudaFuncSetAttribute(gemm_ts<0>, cudaFuncAttributeMaxDynamicSharedMemorySize, SMEM_TOTAL);
        cudaFuncSetAttribute(gemm_ts<1>, cudaFuncAttributeMaxDynamicSharedMemorySize, SMEM_TOTAL);
        cudaFuncSetAttribute(flash_mma,  cudaFuncAttributeMaxDynamicSharedMemorySize, FSMEM);
        attr_set = true;
    }

    __half *Xh, *Wh, *WOh, *Qh, *Kh, *Vh, *AOh;
    cudaGetSymbolAddress((void**)&Xh,  g_Xh);
    cudaGetSymbolAddress((void**)&Wh,  g_Wh);
    cudaGetSymbolAddress((void**)&WOh, g_WOh);
    cudaGetSymbolAddress((void**)&Qh,  g_Qh);
    cudaGetSymbolAddress((void**)&Kh,  g_Kh);
    cudaGetSymbolAddress((void**)&Vh,  g_Vh);
    cudaGetSymbolAddress((void**)&AOh, g_AOh);

    prep_all<<<(N_X + N_W + N_WO) / 256, 256>>>(
        x, wq_w, wq_A, wq_B, wk_w, wv_w, wv_A, wv_B, wo_w, Xh, Wh, WOh);

    gemm_ts<1><<<dim3(NQKV / TN, MTOT / TM), 256, SMEM_TOTAL>>>(
        Xh, Wh, nullptr, NQKV, Qh, Kh, Vh);

    flash_mma<<<dim3(TT / 128, BB * HH), 128, FSMEM>>>(Qh, Kh, Vh, AOh);

    gemm_ts<0><<<dim3(DD / TN, MTOT / TM), 256, SMEM_TOTAL>>>(
        AOh, WOh, out, DD, nullptr, nullptr, nullptr);
}

// round 17
// speedup vs baseline: 1.0336x; 1.0336x over previous
#include <cuda_runtime.h>
#include <cuda_fp16.h>
#include <cstdint>

#define DD    1024
#define TT    2048
#define BB    2
#define MTOT  4096
#define HH    16
#define DHD   64
#define RR    8
#define NQKV  3072

// ---- GEMM tiling: 128x128 CTA tile, k-chunk 64, 3 stages
#define TM 128
#define TN 128
#define KSTEP 64
#define NK (DD / KSTEP)              // 16
#define ROWB 144                     // 128B data + 16B pad
#define TILE_BYTES (128 * ROWB)      // 18432
#define STAGE_BYTES (2 * TILE_BYTES) // 36864
#define NSTAGE 3
#define SMEM_TOTAL (NSTAGE * STAGE_BYTES) // 110592

// ---- flash tiling: 128-key stages, 3 stages; 4 warps x 32 q-rows
#define FROWB 144
#define KB    (128 * FROWB)          // 18432
#define FSTAGE (2 * KB)              // 36864  (K128, V128)
#define FSMEM (3 * FSTAGE)           // 110592 (Q borrows stage2 K region at start)

// Q scale: 1/sqrt(64) * log2(e)  (softmax done in exp2 domain)
#define QSCALE (0.125f * 1.44269504088896f)

// ---- scratch ----
__device__ __half g_Xh [MTOT * DD];
__device__ __half g_Wh [NQKV * DD];
__device__ __half g_WOh[DD * DD];
__device__ __half g_Qh [MTOT * DD];
__device__ __half g_Kh [MTOT * DD];
__device__ __half g_Vh [MTOT * DD];
__device__ __half g_AOh[MTOT * DD];

// ---------------- PTX helpers ----------------
__device__ __forceinline__ uint32_t smem_u32(const void* p) {
    uint32_t a;
    asm("{ .reg .u64 t; cvta.to.shared.u64 t, %1; cvt.u32.u64 %0, t; }" : "=r"(a) : "l"(p));
    return a;
}
#define CP_ASYNC16(dst, src) \
    asm volatile("cp.async.cg.shared.global [%0], [%1], 16;" :: "r"(dst), "l"(src))
#define CP_COMMIT()   asm volatile("cp.async.commit_group;" ::: "memory")
#define CP_WAIT(n)    asm volatile("cp.async.wait_group %0;" :: "n"(n) : "memory")

__device__ __forceinline__ void ldsm4(uint32_t* r, uint32_t addr) {
    asm volatile("ldmatrix.sync.aligned.m8n8.x4.shared.b16 {%0,%1,%2,%3}, [%4];"
                 : "=r"(r[0]), "=r"(r[1]), "=r"(r[2]), "=r"(r[3]) : "r"(addr));
}
__device__ __forceinline__ void ldsm4t(uint32_t* r, uint32_t addr) {
    asm volatile("ldmatrix.sync.aligned.m8n8.x4.trans.shared.b16 {%0,%1,%2,%3}, [%4];"
                 : "=r"(r[0]), "=r"(r[1]), "=r"(r[2]), "=r"(r[3]) : "r"(addr));
}
__device__ __forceinline__ void mma16816(float* c, const uint32_t* a, const uint32_t* b) {
    asm volatile("mma.sync.aligned.m16n8k16.row.col.f32.f16.f16.f32 "
                 "{%0,%1,%2,%3}, {%4,%5,%6,%7}, {%8,%9}, {%0,%1,%2,%3};"
                 : "+f"(c[0]), "+f"(c[1]), "+f"(c[2]), "+f"(c[3])
                 : "r"(a[0]), "r"(a[1]), "r"(a[2]), "r"(a[3]), "r"(b[0]), "r"(b[1]));
}

// ---------------- single fused prep kernel ----------------
#define N_X  (MTOT * DD)
#define N_W  (NQKV * DD)
#define N_WO (DD * DD)
__global__ void prep_all(const float* __restrict__ x,
                         const float* __restrict__ wq, const float* __restrict__ qA,
                         const float* __restrict__ qB, const float* __restrict__ wk,
                         const float* __restrict__ wv, const float* __restrict__ vA,
                         const float* __restrict__ vB, const float* __restrict__ wo,
                         __half* __restrict__ Xh, __half* __restrict__ Wh,
                         __half* __restrict__ WOh) {
    int i = blockIdx.x * blockDim.x + threadIdx.x;
    if (i < N_X) {
        Xh[i] = __float2half_rn(x[i]);
        return;
    }
    i -= N_X;
    if (i < N_W) {
        int o = i / DD, c = i % DD;
        float v;
        if (o < 1024) {
            v = wq[o * DD + c];
#pragma unroll
            for (int r = 0; r < RR; r++) v += 2.0f * qB[o * RR + r] * qA[r * DD + c];
        } else if (o < 2048) {
            v = wk[(o - 1024) * DD + c];
        } else {
            int oo = o - 2048;
            v = wv[oo * DD + c];
#pragma unroll
            for (int r = 0; r < RR; r++) v += 2.0f * vB[oo * RR + r] * vA[r * DD + c];
        }
        Wh[i] = __float2half_rn(v);
        return;
    }
    i -= N_W;
    if (i < N_WO) WOh[i] = __float2half_rn(wo[i]);
}

// ---------------- single-term fp16 GEMM (fp32 accum), k-chunk 64 ----------------
__device__ __forceinline__ void load_stage(
    uint32_t stage_base, const __half* __restrict__ A, const __half* __restrict__ B,
    int m0, int n0, int kc, int tid)
{
#pragma unroll
    for (int t = 0; t < 2; t++) {
        const __half* base = (t == 0 ? A : B) + (size_t)(t == 0 ? m0 : n0) * DD + kc * KSTEP;
        uint32_t dst_tile = stage_base + t * TILE_BYTES;
#pragma unroll
        for (int i = 0; i < 4; i++) {
            int idx = tid + i * 256;            // 0..1023
            int row = idx >> 3, c = idx & 7;    // 128 rows x 8 x 16B
            CP_ASYNC16(dst_tile + row * ROWB + c * 16,
                       (const char*)(base + (size_t)row * DD) + c * 16);
        }
    }
}

// MODE 0: fp32 C.  MODE 1: fused QKV epilogue (per-head fp16, Q scaled into exp2 domain)
template<int MODE>
__global__ __launch_bounds__(256, 2) void gemm_ts(
    const __half* __restrict__ A, const __half* __restrict__ B,
    float* __restrict__ C, int Ntot,
    __half* __restrict__ Qh, __half* __restrict__ Kh, __half* __restrict__ Vh)
{
    extern __shared__ char smem[];
    uint32_t sb = smem_u32(smem);
    int tid = threadIdx.x;
    int wid = tid >> 5, lane = tid & 31;
    int wm = (wid & 3) * 32;
    int wn = (wid >> 2) * 64;
    int m0 = blockIdx.y * TM, n0 = blockIdx.x * TN;

    uint32_t aoff = (uint32_t)(wm + (lane & 15)) * ROWB + (lane >> 4) * 16;
    uint32_t boff = (uint32_t)(wn + (lane & 7) + ((lane >> 4) << 3)) * ROWB
                  + ((lane >> 3) & 1) * 16;

    float acc[2][8][4];
#pragma unroll
    for (int i = 0; i < 2; i++)
#pragma unroll
        for (int j = 0; j < 8; j++)
#pragma unroll
            for (int k = 0; k < 4; k++) acc[i][j][k] = 0.0f;

    load_stage(sb, A, B, m0, n0, 0, tid);
    CP_COMMIT();
    load_stage(sb + STAGE_BYTES, A, B, m0, n0, 1, tid);
    CP_COMMIT();

    int sidx = 0;
    for (int c = 0; c < NK; c++) {
        uint32_t st = sb + sidx * STAGE_BYTES;
        if (c + 1 < NK) { CP_WAIT(1); } else { CP_WAIT(0); }
        __syncthreads();
        if (c + 2 < NK) {
            int s2 = sidx + 2; if (s2 >= NSTAGE) s2 -= NSTAGE;
            load_stage(sb + s2 * STAGE_BYTES, A, B, m0, n0, c + 2, tid);
            CP_COMMIT();
        }

        uint32_t baseA = st + aoff;
        uint32_t baseB = st + TILE_BYTES + boff;

#pragma unroll 2
        for (int kk = 0; kk < 4; kk++) {        // four k16 slices of the k64 chunk
            uint32_t koff = kk * 32;
            uint32_t a[2][4], b[4][4];
#pragma unroll
            for (int mt = 0; mt < 2; mt++)
                ldsm4(a[mt], baseA + mt * 16 * ROWB + koff);
#pragma unroll
            for (int np = 0; np < 4; np++)
                ldsm4(b[np], baseB + np * 16 * ROWB + koff);
#pragma unroll
            for (int mt = 0; mt < 2; mt++)
#pragma unroll
                for (int np = 0; np < 4; np++) {
                    mma16816(acc[mt][np*2],   a[mt], &b[np][0]);
                    mma16816(acc[mt][np*2+1], a[mt], &b[np][2]);
                }
        }
        if (++sidx >= NSTAGE) sidx -= NSTAGE;
    }

    if (MODE == 0) {
        int rbase = m0 + wm + (lane >> 2);
        int cbase = n0 + wn + 2 * (lane & 3);
#pragma unroll
        for (int mt = 0; mt < 2; mt++)
#pragma unroll
            for (int nt = 0; nt < 8; nt++) {
                float* p0 = C + (size_t)(rbase + mt * 16) * Ntot + cbase + nt * 8;
                float* p1 = C + (size_t)(rbase + mt * 16 + 8) * Ntot + cbase + nt * 8;
                *(float2*)p0 = make_float2(acc[mt][nt][0], acc[mt][nt][1]);
                *(float2*)p1 = make_float2(acc[mt][nt][2], acc[mt][nt][3]);
            }
    } else {
        int colbase = n0 + wn;
        int sector = colbase >> 10;
        int h = (colbase & 1023) >> 6;
        int d0 = 2 * (lane & 3);
        float scale = (sector == 0) ? QSCALE : 1.0f;
        __half* D = (sector == 0) ? Qh : (sector == 1) ? Kh : Vh;
#pragma unroll
        for (int mt = 0; mt < 2; mt++) {
            int mrow0 = m0 + wm + (lane >> 2) + mt * 16;
            int mrow1 = mrow0 + 8;
            size_t base0 = ((size_t)((mrow0 >> 11) * HH + h) * TT + (mrow0 & 2047)) * DHD + d0;
            size_t base1 = ((size_t)((mrow1 >> 11) * HH + h) * TT + (mrow1 & 2047)) * DHD + d0;
#pragma unroll
            for (int nt = 0; nt < 8; nt++) {
                *(__half2*)(D + base0 + nt * 8) =
                    __floats2half2_rn(acc[mt][nt][0] * scale, acc[mt][nt][1] * scale);
                *(__half2*)(D + base1 + nt * 8) =
                    __floats2half2_rn(acc[mt][nt][2] * scale, acc[mt][nt][3] * scale);
            }
        }
    }
}

// ---------------- flash attention: 4 warps x 32 q-rows, 128-key stages ----------------
__device__ __forceinline__ void flash_load_kv128(
    uint32_t st, const __half* __restrict__ Kh, const __half* __restrict__ Vh,
    int bh, int k0, int tid)
{
#pragma unroll
    for (int i = 0; i < 8; i++) {
        int idx = tid + i * 128;            // 0..1023
        int row = idx >> 3, c = idx & 7;    // 128 rows x 8 x 16B
        size_t krow = ((size_t)bh * TT + k0 + row) * DHD;
        CP_ASYNC16(st + row * FROWB + c * 16,      (const char*)(Kh + krow) + c * 16);
        CP_ASYNC16(st + KB + row * FROWB + c * 16, (const char*)(Vh + krow) + c * 16);
    }
}

__global__ __launch_bounds__(128, 2) void flash_mma(
    const __half* __restrict__ Qh, const __half* __restrict__ Kh,
    const __half* __restrict__ Vh, __half* __restrict__ AOh)
{
    extern __shared__ char smem[];
    uint32_t sb = smem_u32(smem);
    int tid = threadIdx.x, wid = tid >> 5, lane = tid & 31;
    int qblk = (TT / 128 - 1) - blockIdx.x;   // longest blocks first
    int bh = blockIdx.y;
    int q0 = qblk * 128;
    int wm = wid * 32;                        // warp owns 32 q-rows
    int nit = qblk + 1;                       // 128-key iterations
    int wrow_max = q0 + wm + 31;

    // ---- overlapped prologue: Q (into stage2 K region) + KV0 in one group
    uint32_t qarea = sb + 2 * FSTAGE;
#pragma unroll
    for (int i = 0; i < 8; i++) {
        int idx = tid + i * 128;
        int row = idx >> 3, c = idx & 7;
        size_t qrow = ((size_t)bh * TT + q0 + row) * DHD;
        CP_ASYNC16(qarea + row * FROWB + c * 16, (const char*)(Qh + qrow) + c * 16);
    }
    flash_load_kv128(sb, Kh, Vh, bh, 0, tid);
    CP_COMMIT();                              // G0 = {Q, KV0}
    if (nit > 1) {
        flash_load_kv128(sb + FSTAGE, Kh, Vh, bh, 128, tid);
        CP_COMMIT();                          // G1 = {KV1}
        CP_WAIT(1);                           // Q + KV0 resident
    } else {
        CP_WAIT(0);
    }
    __syncthreads();
    uint32_t qf[2][4][4];
#pragma unroll
    for (int mt = 0; mt < 2; mt++) {
        uint32_t qaddr = qarea + (uint32_t)(wm + mt * 16 + (lane & 15)) * FROWB + (lane >> 4) * 16;
#pragma unroll
        for (int s = 0; s < 4; s++)
            ldsm4(qf[mt][s], qaddr + s * 32);
    }

    float o[2][8][4];
#pragma unroll
    for (int mt = 0; mt < 2; mt++)
#pragma unroll
        for (int j = 0; j < 8; j++)
#pragma unroll
            for (int k = 0; k < 4; k++) o[mt][j][k] = 0.0f;
    float lrow[2][2] = {{0.f, 0.f}, {0.f, 0.f}};

    uint32_t bpat = (uint32_t)((lane & 7) + ((lane >> 4) << 3)) * FROWB + ((lane >> 3) & 1) * 16;
    uint32_t vpat = (uint32_t)(lane & 15) * FROWB + ((lane >> 4) << 4);

    int sidx = 0;
    for (int it = 0; it < nit; it++) {
        uint32_t st = sb + sidx * FSTAGE;
        if (it + 1 < nit) { CP_WAIT(1); } else { CP_WAIT(0); }
        __syncthreads();        // also guards Q-area reuse before it=0's prefetch
        if (it + 2 < nit) {
            int s2 = sidx + 2; if (s2 >= 3) s2 -= 3;
            flash_load_kv128(sb + s2 * FSTAGE, Kh, Vh, bh, (it + 2) * 128, tid);
            CP_COMMIT();
        }

#pragma unroll
        for (int sub = 0; sub < 2; sub++) {
            int kb = it * 128 + sub * 64;
            if (kb > wrow_max) break;       // per-warp causal skip

            uint32_t subK = st + (uint32_t)(sub * 64) * FROWB;
            uint32_t subV = st + KB + (uint32_t)(sub * 64) * FROWB;

            // ---- S = Q K^T for both m16 row-groups (K frags reused)
            float s[2][8][4];
#pragma unroll
            for (int mt = 0; mt < 2; mt++)
#pragma unroll
                for (int j = 0; j < 8; j++)
#pragma unroll
                    for (int k = 0; k < 4; k++) s[mt][j][k] = 0.0f;
            uint32_t baseK = subK + bpat;
#pragma unroll
            for (int ks = 0; ks < 4; ks++) {
                uint32_t koff = ks * 32;
                uint32_t kbf[4][4];
#pragma unroll
                for (int np = 0; np < 4; np++)
                    ldsm4(kbf[np], baseK + np * 16 * FROWB + koff);
#pragma unroll
                for (int mt = 0; mt < 2; mt++)
#pragma unroll
                    for (int np = 0; np < 4; np++) {
                        mma16816(s[mt][np*2],   qf[mt][ks], &kbf[np][0]);
                        mma16816(s[mt][np*2+1], qf[mt][ks], &kbf[np][2]);
                    }
            }

            // ---- mask + static exp2 softmax + pack, per row-group
            uint32_t ph[2][8][2];
#pragma unroll
            for (int mt = 0; mt < 2; mt++) {
                int row0 = q0 + wm + mt * 16 + (lane >> 2);
                if (kb + 63 > row0) {
#pragma unroll
                    for (int j = 0; j < 8; j++) {
                        int colb = kb + j * 8 + 2 * (lane & 3);
                        if (colb     > row0)     s[mt][j][0] = -1e30f;
                        if (colb + 1 > row0)     s[mt][j][1] = -1e30f;
                        if (colb     > row0 + 8) s[mt][j][2] = -1e30f;
                        if (colb + 1 > row0 + 8) s[mt][j][3] = -1e30f;
                    }
                }
#pragma unroll
                for (int j = 0; j < 8; j++) {
                    float p0 = exp2f(s[mt][j][0]), p1 = exp2f(s[mt][j][1]);
                    float p2 = exp2f(s[mt][j][2]), p3 = exp2f(s[mt][j][3]);
                    lrow[mt][0] += p0 + p1; lrow[mt][1] += p2 + p3;
                    __half2 h0 = __floats2half2_rn(p0, p1);
                    __half2 h1 = __floats2half2_rn(p2, p3);
                    ph[mt][j][0] = *(uint32_t*)&h0; ph[mt][j][1] = *(uint32_t*)&h1;
                }
            }

            // ---- O += P V for both row-groups (V frags reused)
            uint32_t baseV = subV + vpat;
#pragma unroll
            for (int ks = 0; ks < 4; ks++) {
                uint32_t roff = ks * 16 * FROWB;
                uint32_t vb[4][4];
#pragma unroll
                for (int np = 0; np < 4; np++)
                    ldsm4t(vb[np], baseV + roff + np * 32);
#pragma unroll
                for (int mt = 0; mt < 2; mt++) {
                    uint32_t ath[4] = { ph[mt][2*ks][0], ph[mt][2*ks][1],
                                        ph[mt][2*ks+1][0], ph[mt][2*ks+1][1] };
#pragma unroll
                    for (int np = 0; np < 4; np++) {
                        mma16816(o[mt][np*2],   ath, &vb[np][0]);
                        mma16816(o[mt][np*2+1], ath, &vb[np][2]);
                    }
                }
            }
        }
        if (++sidx >= 3) sidx -= 3;
    }

    // ---- deferred row-sum reduction (once)
#pragma unroll
    for (int mt = 0; mt < 2; mt++)
#pragma unroll
        for (int g = 0; g < 2; g++) {
            lrow[mt][g] += __shfl_xor_sync(0xffffffff, lrow[mt][g], 1);
            lrow[mt][g] += __shfl_xor_sync(0xffffffff, lrow[mt][g], 2);
        }

    // ---- epilogue: normalize, fp16 AO
    int b = bh >> 4, h = bh & 15;
#pragma unroll
    for (int mt = 0; mt < 2; mt++) {
        float inv0 = 1.0f / lrow[mt][0], inv1 = 1.0f / lrow[mt][1];
        int r0 = q0 + wm + mt * 16 + (lane >> 2);
        size_t base0 = (size_t)(b * TT + r0) * DD + h * DHD + 2 * (lane & 3);
        size_t base1 = base0 + (size_t)8 * DD;
#pragma unroll
        for (int j = 0; j < 8; j++) {
            *(__half2*)(AOh + base0 + j * 8) =
                __floats2half2_rn(o[mt][j][0] * inv0, o[mt][j][1] * inv0);
            *(__half2*)(AOh + base1 + j * 8) =
                __floats2half2_rn(o[mt][j][2] * inv1, o[mt][j][3] * inv1);
        }
    }
}

// ---------------- launch ----------------
extern "C" void kernel_launch(void* const* d_in, const int* in_sizes, int n_in,
                              void* d_out, int out_size) {
    const float* x    = (const float*)d_in[0];
    const float* wq_w = (const float*)d_in[2];
    const float* wq_A = (const float*)d_in[3];
    const float* wq_B = (const float*)d_in[4];
    const float* wk_w = (const float*)d_in[5];
    const float* wv_w = (const float*)d_in[6];
    const float* wv_A = (const float*)d_in[7];
    const float* wv_B = (const float*)d_in[8];
    const float* wo_w = (const float*)d_in[9];
    float* out = (float*)d_out;

    static bool attr_set = false;
    if (!attr_set) {
        cudaFuncSetAttribute(gemm_ts<0>, cudaFuncAttributeMaxDynamicSharedMemorySize, SMEM_TOTAL);
        cudaFuncSetAttribute(gemm_ts<1>, cudaFuncAttributeMaxDynamicSharedMemorySize, SMEM_TOTAL);
        cudaFuncSetAttribute(flash_mma,  cudaFuncAttributeMaxDynamicSharedMemorySize, FSMEM);
        attr_set = true;
    }

    __half *Xh, *Wh, *WOh, *Qh, *Kh, *Vh, *AOh;
    cudaGetSymbolAddress((void**)&Xh,  g_Xh);
    cudaGetSymbolAddress((void**)&Wh,  g_Wh);
    cudaGetSymbolAddress((void**)&WOh, g_WOh);
    cudaGetSymbolAddress((void**)&Qh,  g_Qh);
    cudaGetSymbolAddress((void**)&Kh,  g_Kh);
    cudaGetSymbolAddress((void**)&Vh,  g_Vh);
    cudaGetSymbolAddress((void**)&AOh, g_AOh);

    prep_all<<<(N_X + N_W + N_WO) / 256, 256>>>(
        x, wq_w, wq_A, wq_B, wk_w, wv_w, wv_A, wv_B, wo_w, Xh, Wh, WOh);

    gemm_ts<1><<<dim3(NQKV / TN, MTOT / TM), 256, SMEM_TOTAL>>>(
        Xh, Wh, nullptr, NQKV, Qh, Kh, Vh);

    flash_mma<<<dim3(TT / 128, BB * HH), 128, FSMEM>>>(Qh, Kh, Vh, AOh);

    gemm_ts<0><<<dim3(DD / TN, MTOT / TM), 256, SMEM_TOTAL>>>(
        AOh, WOh, out, DD, nullptr, nullptr, nullptr);
}